// round 14
// baseline (speedup 1.0000x reference)
#include <cuda_runtime.h>
#include <cuda_bf16.h>
#include <math_constants.h>

// SelfContactSmall: vertices [B=2, N, 3] f32, geomask [N, N] (bool -> i32).
// out = concat(v2v_min [B*N] f32, in_contact [B*N] as 0.0/1.0 f32)
//
// v2v_min[b][j] = sq_j + min over masked i of (sq_i - 2*dot(v_i, v_j))
//
// 4 columns per thread (LDS of shared row data amortized 4x).
// Mask applied via NaN-injection: (mask-1) is all-ones when masked out;
// OR into the float makes it NaN, and fminf(m, NaN) == m.
// Partial mins merged via order-preserving-mapped atomicMin.

#define BATCH    2
#define THREADS  256
#define CPT      4
#define ROWTILE  128
#define ISPLITS  40
#define THRES2   0.0004f   // 0.02^2

#define MAPPED_INF 0xFF800000u   // map_f2u(+inf)

__device__ __forceinline__ unsigned int map_f2u(float f) {
    int b = __float_as_int(f);
    return (unsigned int)(b ^ ((b >> 31) | 0x80000000));
}
__device__ __forceinline__ float unmap_u2f(unsigned int u) {
    int b = (u & 0x80000000u) ? (int)(u ^ 0x80000000u) : ~(int)u;
    return __int_as_float(b);
}

// ---------------------------------------------------------------------------
// Kernel 1: init mapped-min region of d_out.
// ---------------------------------------------------------------------------
__global__ void sc_init_kernel(unsigned int* __restrict__ out_bits, int n_total) {
    int i = blockIdx.x * blockDim.x + threadIdx.x;
    if (i < n_total) out_bits[i] = MAPPED_INF;
}

// ---------------------------------------------------------------------------
// Kernel 2: masked column-min of (sq_i - 2*dot), 4 cols/thread, both batches.
// ---------------------------------------------------------------------------
__global__ __launch_bounds__(THREADS)
void sc_min_kernel(const float* __restrict__ verts,
                   const int*   __restrict__ gmask,
                   unsigned int* __restrict__ out_bits,
                   int N) {
    __shared__ float4 sv0[ROWTILE];
    __shared__ float4 sv1[ROWTILE];

    const int tid     = threadIdx.x;
    const int colbase = blockIdx.x * (THREADS * CPT) + tid;

    // Clamped columns: threads past N redundantly (and correctly) recompute
    // column N-1, so no validity guards are needed anywhere.
    int col[CPT];
    #pragma unroll
    for (int k = 0; k < CPT; k++)
        col[k] = min(colbase + k * THREADS, N - 1);

    // Column coords, both batches.
    float x0[CPT], y0[CPT], z0[CPT], x1[CPT], y1[CPT], z1[CPT];
    #pragma unroll
    for (int k = 0; k < CPT; k++) {
        const int j = col[k];
        x0[k] = verts[3 * j + 0];
        y0[k] = verts[3 * j + 1];
        z0[k] = verts[3 * j + 2];
        x1[k] = verts[3 * (size_t)(N + j) + 0];
        y1[k] = verts[3 * (size_t)(N + j) + 1];
        z1[k] = verts[3 * (size_t)(N + j) + 2];
    }

    float m0[CPT], m1[CPT];
    #pragma unroll
    for (int k = 0; k < CPT; k++) { m0[k] = CUDART_INF_F; m1[k] = CUDART_INF_F; }

    const int chunk = (N + ISPLITS - 1) / ISPLITS;
    const int ibeg  = blockIdx.y * chunk;
    const int iend  = min(N, ibeg + chunk);

    for (int i0 = ibeg; i0 < iend; i0 += ROWTILE) {
        const int cnt = min(ROWTILE, iend - i0);

        __syncthreads();
        // Stage rows: float4 (-2x, -2y, -2z, sq) per batch.
        for (int t = tid; t < cnt * 2; t += THREADS) {
            const int r = t >> 1;
            const int b = t & 1;
            const float* vp = verts + 3 * (size_t)((b ? N : 0) + i0 + r);
            const float x = vp[0], y = vp[1], z = vp[2];
            const float4 v = make_float4(-2.0f * x, -2.0f * y, -2.0f * z,
                                         fmaf(z, z, fmaf(y, y, x * x)));
            if (b) sv1[r] = v; else sv0[r] = v;
        }
        __syncthreads();

        const int* gm = gmask + (size_t)i0 * N;

        #pragma unroll 2
        for (int r = 0; r < cnt; r++) {
            // Issue all mask loads first (MLP).
            int okm[CPT];
            #pragma unroll
            for (int k = 0; k < CPT; k++)
                okm[k] = gm[col[k]] - 1;   // 1 -> 0x00000000, 0 -> 0xFFFFFFFF

            const float4 a = sv0[r];
            const float4 b = sv1[r];

            #pragma unroll
            for (int k = 0; k < CPT; k++) {
                float d0 = fmaf(a.z, z0[k], fmaf(a.y, y0[k], fmaf(a.x, x0[k], a.w)));
                float d1 = fmaf(b.z, z1[k], fmaf(b.y, y1[k], fmaf(b.x, x1[k], b.w)));
                // NaN-inject when masked out; fminf ignores NaN.
                d0 = __int_as_float(__float_as_int(d0) | okm[k]);
                d1 = __int_as_float(__float_as_int(d1) | okm[k]);
                m0[k] = fminf(m0[k], d0);
                m1[k] = fminf(m1[k], d1);
            }
            gm += N;
        }
    }

    #pragma unroll
    for (int k = 0; k < CPT; k++) {
        atomicMin(&out_bits[col[k]],     map_f2u(m0[k]));
        atomicMin(&out_bits[N + col[k]], map_f2u(m1[k]));
    }
}

// ---------------------------------------------------------------------------
// Kernel 3: unmap, add sq_j, write mins + contact flags.
// ---------------------------------------------------------------------------
__global__ void sc_final_kernel(float* __restrict__ out,
                                const float* __restrict__ verts,
                                int n_total) {
    const int idx = blockIdx.x * blockDim.x + threadIdx.x;   // over B*N
    if (idx < n_total) {
        const float x = verts[3 * (size_t)idx + 0];
        const float y = verts[3 * (size_t)idx + 1];
        const float z = verts[3 * (size_t)idx + 2];
        const float sq = fmaf(z, z, fmaf(y, y, x * x));

        const unsigned int u = ((const unsigned int*)out)[idx];
        const float m = unmap_u2f(u) + sq;

        out[idx]           = m;
        out[n_total + idx] = (m < THRES2) ? 1.0f : 0.0f;
    }
}

// ---------------------------------------------------------------------------
extern "C" void kernel_launch(void* const* d_in, const int* in_sizes, int n_in,
                              void* d_out, int out_size) {
    const float* verts = (const float*)d_in[0];   // [B, N, 3] f32
    const int*   gmask = (const int*)d_in[1];     // [N, N] bool -> i32

    float* out = (float*)d_out;
    const int N = in_sizes[0] / (BATCH * 3);      // 10475
    const int n_total = BATCH * N;                // 20950

    {
        int blocks = (n_total + THREADS - 1) / THREADS;
        sc_init_kernel<<<blocks, THREADS>>>((unsigned int*)out, n_total);
    }
    {
        dim3 grid((N + THREADS * CPT - 1) / (THREADS * CPT), ISPLITS);
        sc_min_kernel<<<grid, THREADS>>>(verts, gmask, (unsigned int*)out, N);
    }
    {
        int blocks = (n_total + THREADS - 1) / THREADS;
        sc_final_kernel<<<blocks, THREADS>>>(out, verts, n_total);
    }
}

// round 15
// speedup vs baseline: 2.3780x; 2.3780x over previous
#include <cuda_runtime.h>
#include <cuda_bf16.h>
#include <math_constants.h>

// SelfContactSmall: vertices [B=2, N, 3] f32, geomask [N, N] (bool -> i32).
// out = concat(v2v_min [B*N] f32, in_contact [B*N] as 0.0/1.0 f32)
//
// v2v_min[b][j] = sq_j + min over masked i of (sq_i - 2*dot(v_i, v_j))
//
// One thread = one column j (both batches). Row data staged in SMEM as
// float4 (-2x, -2y, -2z, sq) -> broadcast LDS (no bank penalty).
// Mask is software-pipelined: groups of 8 rows, all 8 streaming LDGs
// issued back-to-back before any math (MLP >= 8 hides DRAM latency).
// Partial mins merged via order-preserving-mapped atomicMin.

#define BATCH    2
#define THREADS  256
#define ROWTILE  128
#define GROUP    8
#define ISPLITS  16
#define THRES2   0.0004f   // 0.02^2

#define MAPPED_INF 0xFF800000u   // map_f2u(+inf)

__device__ __forceinline__ unsigned int map_f2u(float f) {
    int b = __float_as_int(f);
    return (unsigned int)(b ^ ((b >> 31) | 0x80000000));
}
__device__ __forceinline__ float unmap_u2f(unsigned int u) {
    int b = (u & 0x80000000u) ? (int)(u ^ 0x80000000u) : ~(int)u;
    return __int_as_float(b);
}

// ---------------------------------------------------------------------------
// Kernel 1: init mapped-min region of d_out.
// ---------------------------------------------------------------------------
__global__ void sc_init_kernel(unsigned int* __restrict__ out_bits, int n_total) {
    int i = blockIdx.x * blockDim.x + threadIdx.x;
    if (i < n_total) out_bits[i] = MAPPED_INF;
}

// ---------------------------------------------------------------------------
// Kernel 2: masked column-min of (sq_i - 2*dot), 1 col/thread, both batches.
// ---------------------------------------------------------------------------
__global__ __launch_bounds__(THREADS)
void sc_min_kernel(const float* __restrict__ verts,
                   const int*   __restrict__ gmask,
                   unsigned int* __restrict__ out_bits,
                   int N) {
    __shared__ float4 sv0[ROWTILE];
    __shared__ float4 sv1[ROWTILE];

    const int tid = threadIdx.x;
    // Clamp (not guard): overflow threads redundantly compute column N-1;
    // duplicate atomicMin results are identical, so this is safe.
    const int j = min(blockIdx.x * THREADS + tid, N - 1);

    const int chunk = (N + ISPLITS - 1) / ISPLITS;
    const int ibeg  = blockIdx.y * chunk;
    const int iend  = min(N, ibeg + chunk);

    // Column coords, both batches.
    const float x0 = verts[3 * j + 0];
    const float y0 = verts[3 * j + 1];
    const float z0 = verts[3 * j + 2];
    const float x1 = verts[3 * (size_t)(N + j) + 0];
    const float y1 = verts[3 * (size_t)(N + j) + 1];
    const float z1 = verts[3 * (size_t)(N + j) + 2];

    float m0 = CUDART_INF_F, m1 = CUDART_INF_F;

    for (int i0 = ibeg; i0 < iend; i0 += ROWTILE) {
        const int cnt = min(ROWTILE, iend - i0);

        __syncthreads();
        // Stage rows: float4 (-2x, -2y, -2z, sq) per batch.
        for (int t = tid; t < cnt * 2; t += THREADS) {
            const int r = t >> 1;
            const int b = t & 1;
            const float* vp = verts + 3 * (size_t)((b ? N : 0) + i0 + r);
            const float x = vp[0], y = vp[1], z = vp[2];
            const float4 v = make_float4(-2.0f * x, -2.0f * y, -2.0f * z,
                                         fmaf(z, z, fmaf(y, y, x * x)));
            if (b) sv1[r] = v; else sv0[r] = v;
        }
        __syncthreads();

        const int* gm = gmask + (size_t)i0 * N + j;

        int r = 0;
        // Fast path: groups of GROUP rows; all mask LDGs batched up front.
        for (; r + GROUP <= cnt; r += GROUP) {
            int okm[GROUP];
            #pragma unroll
            for (int u = 0; u < GROUP; u++)
                okm[u] = __ldcs(gm + (size_t)u * N) - 1;  // 1->0, 0->0xFFFFFFFF
            gm += (size_t)GROUP * N;

            #pragma unroll
            for (int u = 0; u < GROUP; u++) {
                const float4 a = sv0[r + u];
                const float4 b = sv1[r + u];
                float d0 = fmaf(a.z, z0, fmaf(a.y, y0, fmaf(a.x, x0, a.w)));
                float d1 = fmaf(b.z, z1, fmaf(b.y, y1, fmaf(b.x, x1, b.w)));
                // NaN-inject when masked out; fminf(m, NaN) == m.
                d0 = __int_as_float(__float_as_int(d0) | okm[u]);
                d1 = __int_as_float(__float_as_int(d1) | okm[u]);
                m0 = fminf(m0, d0);
                m1 = fminf(m1, d1);
            }
        }
        // Tail rows.
        for (; r < cnt; r++) {
            const int okm = __ldcs(gm) - 1;
            gm += N;
            const float4 a = sv0[r];
            const float4 b = sv1[r];
            float d0 = fmaf(a.z, z0, fmaf(a.y, y0, fmaf(a.x, x0, a.w)));
            float d1 = fmaf(b.z, z1, fmaf(b.y, y1, fmaf(b.x, x1, b.w)));
            d0 = __int_as_float(__float_as_int(d0) | okm);
            d1 = __int_as_float(__float_as_int(d1) | okm);
            m0 = fminf(m0, d0);
            m1 = fminf(m1, d1);
        }
    }

    atomicMin(&out_bits[j],     map_f2u(m0));
    atomicMin(&out_bits[N + j], map_f2u(m1));
}

// ---------------------------------------------------------------------------
// Kernel 3: unmap, add sq_j, write mins + contact flags.
// ---------------------------------------------------------------------------
__global__ void sc_final_kernel(float* __restrict__ out,
                                const float* __restrict__ verts,
                                int n_total) {
    const int idx = blockIdx.x * blockDim.x + threadIdx.x;   // over B*N
    if (idx < n_total) {
        const float x = verts[3 * (size_t)idx + 0];
        const float y = verts[3 * (size_t)idx + 1];
        const float z = verts[3 * (size_t)idx + 2];
        const float sq = fmaf(z, z, fmaf(y, y, x * x));

        const unsigned int u = ((const unsigned int*)out)[idx];
        const float m = unmap_u2f(u) + sq;

        out[idx]           = m;
        out[n_total + idx] = (m < THRES2) ? 1.0f : 0.0f;
    }
}

// ---------------------------------------------------------------------------
extern "C" void kernel_launch(void* const* d_in, const int* in_sizes, int n_in,
                              void* d_out, int out_size) {
    const float* verts = (const float*)d_in[0];   // [B, N, 3] f32
    const int*   gmask = (const int*)d_in[1];     // [N, N] bool -> i32

    float* out = (float*)d_out;
    const int N = in_sizes[0] / (BATCH * 3);      // 10475
    const int n_total = BATCH * N;                // 20950

    {
        int blocks = (n_total + THREADS - 1) / THREADS;
        sc_init_kernel<<<blocks, THREADS>>>((unsigned int*)out, n_total);
    }
    {
        dim3 grid((N + THREADS - 1) / THREADS, ISPLITS);
        sc_min_kernel<<<grid, THREADS>>>(verts, gmask, (unsigned int*)out, N);
    }
    {
        int blocks = (n_total + THREADS - 1) / THREADS;
        sc_final_kernel<<<blocks, THREADS>>>(out, verts, n_total);
    }
}